// round 12
// baseline (speedup 1.0000x reference)
#include <cuda_runtime.h>
#include <cuda_fp16.h>
#include <math.h>
#include <stdint.h>

#define NSP   10000
#define NLOC  50000
#define EOBS  500000
#define ENEAR 400000
#define HID   128
#define HEADS 4
#define CH    32

#define NB_CNT  1954                      // (EOBS+255)/256
#define NB_FEAT 313                       // (NSP+31)/32
#define NB_G64  1563                      // (NLOC+31)/32
#define NB_WD   8
#define NB_GEMM 391                       // (NLOC+127)/128
#define AGGR_BLOCKS 7500                  // (NSP+NLOC)*32/256

// ---------------- scratch (static device globals) ----------------
__device__ float  g_hsp  [NSP  * HID];
__device__ float  g_hloc [NLOC * HID];
__device__ __half g_PlocA[NLOC * HID];
__device__ __half g_PlocC[NLOC * HID];
__device__ __half g_PspB [NSP  * HID];
__device__ float g_als0[NLOC * HEADS];
__device__ float g_ald0[NSP  * HEADS];
__device__ float g_als1[NSP  * HEADS];
__device__ float g_ald1[NLOC * HEADS];
__device__ float g_als2[NLOC * HEADS];
__device__ float g_ald2[NLOC * HEADS];
__device__ float g_wd  [2 * 2 * HEADS * HID];   // [layer][rel(0=obs,1=obsat)][h][k]

// CSR scratch
__device__ int g_rp_obs  [NSP + 1];
__device__ int g_rp_obsat[NLOC + 1];
__device__ int g_rp_near [NLOC + 1];
__device__ int g_cur_obs  [NSP];
__device__ int g_cur_obsat[NLOC];
__device__ int g_cur_near [NLOC];
__device__ int g_deg_obs  [NSP];
__device__ int g_deg_obsat[NLOC];
__device__ int g_deg_near [NLOC];
__device__ int g_csrc_obs  [EOBS];
__device__ int g_csrc_obsat[EOBS];
__device__ int g_csrc_near [ENEAR];

__device__ __forceinline__ float lrelu(float x) { return x > 0.f ? x : 0.2f * x; }

__device__ __forceinline__ uint32_t f2tf32(float f) {
    uint32_t r;
    asm("cvt.rna.tf32.f32 %0, %1;" : "=r"(r) : "f"(f));
    return r;
}

// ---------------- tf32 GEMM body + attention-logit epilogue; P stored fp16 ----------------
#define WPAD 136
__device__ void gemm_tc_body(int bx, const float* __restrict__ A, const float* __restrict__ W,
                             const float* __restrict__ avs, const float* __restrict__ avd,
                             __half* __restrict__ C, float* __restrict__ als,
                             float* __restrict__ ald, int M) {
    __shared__ __align__(16) uint32_t Ws[64 * WPAD];   // align: uint4 stores below
    if (bx * 128 >= M) return;
    int warp = threadIdx.x >> 5, lane = threadIdx.x & 31;
    int gid = lane >> 2, tig = lane & 3;
    int ra = bx * 128 + warp * 16 + gid;
    int rb = ra + 8;
    bool va = ra < M, vb = rb < M;
    const float* Aa = A + (size_t)(va ? ra : 0) * HID;
    const float* Ab = A + (size_t)(vb ? rb : 0) * HID;

    float c[16][4];
    #pragma unroll
    for (int t = 0; t < 16; ++t) { c[t][0] = c[t][1] = c[t][2] = c[t][3] = 0.f; }

    for (int kc = 0; kc < 2; ++kc) {
        int kbase = kc * 64;
        __syncthreads();
        // vectorized W staging: float4 load -> 4x cvt -> uint4 store
        for (int i = threadIdx.x; i < 64 * 32; i += 256) {
            int k = i >> 5, n4 = i & 31;
            float4 w4 = ((const float4*)(W + (size_t)(kbase + k) * HID))[n4];
            uint4 u = make_uint4(f2tf32(w4.x), f2tf32(w4.y), f2tf32(w4.z), f2tf32(w4.w));
            *(uint4*)&Ws[k * WPAD + n4 * 4] = u;       // k*WPAD*4 = k*544 ≡ 0 mod 16
        }
        __syncthreads();
        #pragma unroll
        for (int k8 = 0; k8 < 8; ++k8) {
            int k0 = kbase + k8 * 8;
            int ks = k8 * 8;
            uint32_t a0 = f2tf32(Aa[k0 + tig]);
            uint32_t a1 = f2tf32(Ab[k0 + tig]);
            uint32_t a2 = f2tf32(Aa[k0 + 4 + tig]);
            uint32_t a3 = f2tf32(Ab[k0 + 4 + tig]);
            const uint32_t* b0row = Ws + (ks + tig) * WPAD + gid;
            const uint32_t* b1row = Ws + (ks + 4 + tig) * WPAD + gid;
            #pragma unroll
            for (int t = 0; t < 16; ++t) {
                uint32_t b0 = b0row[t * 8];
                uint32_t b1 = b1row[t * 8];
                asm volatile(
                    "mma.sync.aligned.m16n8k8.row.col.f32.tf32.tf32.f32 "
                    "{%0,%1,%2,%3}, {%4,%5,%6,%7}, {%8,%9}, {%0,%1,%2,%3};"
                    : "+f"(c[t][0]), "+f"(c[t][1]), "+f"(c[t][2]), "+f"(c[t][3])
                    : "r"(a0), "r"(a1), "r"(a2), "r"(a3), "r"(b0), "r"(b1));
            }
        }
    }

    #pragma unroll
    for (int t = 0; t < 16; ++t) {
        int col = t * 8 + 2 * tig;
        if (va) *(__half2*)(C + (size_t)ra * HID + col) = __floats2half2_rn(c[t][0], c[t][1]);
        if (vb) *(__half2*)(C + (size_t)rb * HID + col) = __floats2half2_rn(c[t][2], c[t][3]);
    }

    {
        float pa[4] = {0, 0, 0, 0}, pb[4] = {0, 0, 0, 0};
        #pragma unroll
        for (int t = 0; t < 16; ++t) {
            int col = t * 8 + 2 * tig;
            float w0 = avs[col], w1 = avs[col + 1];
            pa[t >> 2] += c[t][0] * w0 + c[t][1] * w1;
            pb[t >> 2] += c[t][2] * w0 + c[t][3] * w1;
        }
        #pragma unroll
        for (int hh = 0; hh < 4; ++hh) {
            pa[hh] += __shfl_xor_sync(~0u, pa[hh], 1);
            pa[hh] += __shfl_xor_sync(~0u, pa[hh], 2);
            pb[hh] += __shfl_xor_sync(~0u, pb[hh], 1);
            pb[hh] += __shfl_xor_sync(~0u, pb[hh], 2);
        }
        if (tig == 0) {
            if (va) ((float4*)als)[ra] = make_float4(pa[0], pa[1], pa[2], pa[3]);
            if (vb) ((float4*)als)[rb] = make_float4(pb[0], pb[1], pb[2], pb[3]);
        }
        if (avd) {
            float qa[4] = {0, 0, 0, 0}, qb[4] = {0, 0, 0, 0};
            #pragma unroll
            for (int t = 0; t < 16; ++t) {
                int col = t * 8 + 2 * tig;
                float w0 = avd[col], w1 = avd[col + 1];
                qa[t >> 2] += c[t][0] * w0 + c[t][1] * w1;
                qb[t >> 2] += c[t][2] * w0 + c[t][3] * w1;
            }
            #pragma unroll
            for (int hh = 0; hh < 4; ++hh) {
                qa[hh] += __shfl_xor_sync(~0u, qa[hh], 1);
                qa[hh] += __shfl_xor_sync(~0u, qa[hh], 2);
                qb[hh] += __shfl_xor_sync(~0u, qb[hh], 1);
                qb[hh] += __shfl_xor_sync(~0u, qb[hh], 2);
            }
            if (tig == 0) {
                if (va) ((float4*)ald)[ra] = make_float4(qa[0], qa[1], qa[2], qa[3]);
                if (vb) ((float4*)ald)[rb] = make_float4(qb[0], qb[1], qb[2], qb[3]);
            }
        }
    }
}

__device__ __forceinline__ void gemm_rel_dispatch(int bx, int rel,
        const float* hsp, const float* hloc, const float* Wbase, const float* asbase,
        const float* ad2, __half* PlocA, __half* PspB, __half* PlocC,
        float* als0, float* als1, float* als2, float* ald2o) {
    if (rel == 0)
        gemm_tc_body(bx, hloc, Wbase, asbase, nullptr, PlocA, als0, nullptr, NLOC);
    else if (rel == 1)
        gemm_tc_body(bx, hsp, Wbase + HID * HID, asbase + HID, nullptr, PspB, als1, nullptr, NSP);
    else
        gemm_tc_body(bx, hloc, Wbase + 2 * HID * HID, asbase + 2 * HID, ad2, PlocC, als2, ald2o, NLOC);
}

// standalone GEMM kernel (layer 1)
__global__ void __launch_bounds__(256)
gemm_tc_fused(const float* __restrict__ hsp, const float* __restrict__ hloc,
              const float* __restrict__ Wbase, const float* __restrict__ asbase,
              const float* __restrict__ ad2,
              __half* __restrict__ PlocA, __half* __restrict__ PspB, __half* __restrict__ PlocC,
              float* __restrict__ als0, float* __restrict__ als1,
              float* __restrict__ als2, float* __restrict__ ald2o) {
    gemm_rel_dispatch(blockIdx.x, blockIdx.z, hsp, hloc, Wbase, asbase, ad2,
                      PlocA, PspB, PlocC, als0, als1, als2, ald2o);
}

// ---------------- feature bodies (256 threads, 32 rows/block) ----------------
__device__ void feat_sp_body(int fb, const int* __restrict__ sp_idx,
                             const float* __restrict__ emb, const float* __restrict__ grp,
                             const float* __restrict__ W, const float* __restrict__ b,
                             float* __restrict__ C, float* sbuf) {
    int half = threadIdx.x >> 7;
    int j = threadIdx.x & 127;
    int row0 = fb * 32 + half * 16;
    float (*As)[64] = (float (*)[64])(sbuf + half * 16 * 64);
    for (int i = j; i < 16 * 64; i += 128) {
        int r = i >> 6, k = i & 63;
        int m = row0 + r;
        float v = 0.f;
        if (m < NSP) {
            if (k < 48) v = emb[(size_t)sp_idx[m] * 48 + k];
            else        v = grp[(size_t)m * 16 + (k - 48)];
        }
        As[r][k] = v;
    }
    __syncthreads();
    float acc[16];
    #pragma unroll
    for (int r = 0; r < 16; ++r) acc[r] = 0.f;
    const float4* As4 = (const float4*)&As[0][0];
    #pragma unroll 4
    for (int k4 = 0; k4 < 16; ++k4) {
        int k = k4 * 4;
        float w0 = W[(k + 0) * HID + j];
        float w1 = W[(k + 1) * HID + j];
        float w2 = W[(k + 2) * HID + j];
        float w3 = W[(k + 3) * HID + j];
        #pragma unroll
        for (int r = 0; r < 16; ++r) {
            float4 a = As4[r * 16 + k4];
            acc[r] += a.x * w0 + a.y * w1 + a.z * w2 + a.w * w3;
        }
    }
    float bj = b[j];
    #pragma unroll
    for (int r = 0; r < 16; ++r) {
        int m = row0 + r;
        if (m < NSP) C[(size_t)m * HID + j] = acc[r] + bj;
    }
}

__device__ void gemm64_body(int gb, const float* __restrict__ A, const float* __restrict__ W,
                            const float* __restrict__ b, float* __restrict__ C, int M,
                            float* sbuf) {
    int half = threadIdx.x >> 7;
    int j = threadIdx.x & 127;
    int row0 = gb * 32 + half * 16;
    float (*As)[64] = (float (*)[64])(sbuf + half * 16 * 64);
    for (int i = j; i < 16 * 64; i += 128) {
        int r = i >> 6, k = i & 63;
        int m = row0 + r;
        As[r][k] = (m < M) ? A[(size_t)m * 64 + k] : 0.f;
    }
    __syncthreads();
    float acc[16];
    #pragma unroll
    for (int r = 0; r < 16; ++r) acc[r] = 0.f;
    const float4* As4 = (const float4*)&As[0][0];
    #pragma unroll 4
    for (int k4 = 0; k4 < 16; ++k4) {
        int k = k4 * 4;
        float w0 = W[(k + 0) * HID + j];
        float w1 = W[(k + 1) * HID + j];
        float w2 = W[(k + 2) * HID + j];
        float w3 = W[(k + 3) * HID + j];
        #pragma unroll
        for (int r = 0; r < 16; ++r) {
            float4 a = As4[r * 16 + k4];
            acc[r] += a.x * w0 + a.y * w1 + a.z * w2 + a.w * w3;
        }
    }
    float bj = b[j];
    #pragma unroll
    for (int r = 0; r < 16; ++r) {
        int m = row0 + r;
        if (m < M) C[(size_t)m * HID + j] = acc[r] + bj;
    }
}

// ---------------- fill ----------------
__global__ void fill3_kernel(int* __restrict__ p0, int n0, int* __restrict__ p1, int n1,
                             int* __restrict__ p2, int n2) {
    int i = blockIdx.x * blockDim.x + threadIdx.x;
    if (i < n0) p0[i] = 0;
    if (i < n1) p1[i] = 0;
    if (i < n2) p2[i] = 0;
}

// ---------------- stage A: count3 || feat_sp || gemm64 || wd_all ----------------
__global__ void __launch_bounds__(256)
stageA_kernel(const int* __restrict__ e0, const int* __restrict__ e1, const int* __restrict__ e2,
              int* __restrict__ d0, int* __restrict__ d1, int* __restrict__ d2,
              const int* __restrict__ sp_idx, const float* __restrict__ emb,
              const float* __restrict__ grp, const float* __restrict__ spw,
              const float* __restrict__ spb, const float* __restrict__ locx,
              const float* __restrict__ locw, const float* __restrict__ locb,
              float* __restrict__ hsp, float* __restrict__ hloc,
              const float* __restrict__ gatw, const float* __restrict__ gatad,
              float* __restrict__ wd) {
    __shared__ __align__(16) float sbuf[2 * 16 * 64];  // align: float4 reads in bodies
    int blk = blockIdx.x;
    if (blk < NB_CNT) {
        int e = blk * 256 + threadIdx.x;
        if (e < EOBS) {
            atomicAdd(&d0[e0[EOBS + e]], 1);
            atomicAdd(&d1[e1[EOBS + e]], 1);
        }
        if (e < ENEAR) atomicAdd(&d2[e2[ENEAR + e]], 1);
    } else if (blk < NB_CNT + NB_FEAT) {
        feat_sp_body(blk - NB_CNT, sp_idx, emb, grp, spw, spb, hsp, sbuf);
    } else if (blk < NB_CNT + NB_FEAT + NB_G64) {
        gemm64_body(blk - NB_CNT - NB_FEAT, locx, locw, locb, hloc, NLOC, sbuf);
    } else {
        int t = (blk - NB_CNT - NB_FEAT - NB_G64) * 256 + threadIdx.x;
        if (t < 2048) {
            int l = t >> 10, rem = t & 1023, r = rem >> 9, rem2 = rem & 511,
                h = rem2 >> 7, k = rem2 & 127;
            const float* W  = gatw  + ((size_t)l * 3 + r) * HID * HID;
            const float* ad = gatad + ((size_t)l * 3 + r) * HID;
            float s = 0.f;
            #pragma unroll
            for (int c = 0; c < 32; ++c) s += W[k * HID + h * CH + c] * ad[h * CH + c];
            wd[t] = s;
        }
    }
}

// ---------------- 256-thread scan (8 warps) ----------------
__device__ void scan_one256(const int* __restrict__ deg, int* __restrict__ rowptr,
                            int* __restrict__ cursor, int n, int* warpsums, int* carry_p) {
    int lane = threadIdx.x & 31, wid = threadIdx.x >> 5;
    if (threadIdx.x == 0) *carry_p = 0;
    __syncthreads();
    for (int base = 0; base < n; base += 256) {
        int i = base + (int)threadIdx.x;
        int v = (i < n) ? deg[i] : 0;
        int x = v;
        #pragma unroll
        for (int off = 1; off < 32; off <<= 1) {
            int t = __shfl_up_sync(~0u, x, off);
            if (lane >= off) x += t;
        }
        if (lane == 31) warpsums[wid] = x;
        __syncthreads();
        if (wid == 0) {
            int s = (lane < 8) ? warpsums[lane] : 0;
            #pragma unroll
            for (int off = 1; off < 8; off <<= 1) {
                int t = __shfl_up_sync(~0u, s, off);
                if (lane >= off) s += t;
            }
            if (lane < 8) warpsums[lane] = s;
        }
        __syncthreads();
        int warpoff = wid ? warpsums[wid - 1] : 0;
        int excl = x - v + warpoff;
        int carry = *carry_p;
        if (i < n) {
            int o = carry + excl;
            rowptr[i] = o;
            cursor[i] = o;
        }
        __syncthreads();
        if (threadIdx.x == 0) *carry_p = carry + warpsums[7];
        __syncthreads();
    }
    if (threadIdx.x == 0) rowptr[n] = *carry_p;
}

// ---------------- stage B: scan3 || gemm_tc(layer 0) ----------------
__global__ void __launch_bounds__(256)
stageB_kernel(const int* __restrict__ d0, int* __restrict__ r0, int* __restrict__ c0,
              const int* __restrict__ d1, int* __restrict__ r1, int* __restrict__ c1,
              const int* __restrict__ d2, int* __restrict__ r2, int* __restrict__ c2,
              const float* __restrict__ hsp, const float* __restrict__ hloc,
              const float* __restrict__ Wbase, const float* __restrict__ asbase,
              const float* __restrict__ ad2,
              __half* __restrict__ PlocA, __half* __restrict__ PspB, __half* __restrict__ PlocC,
              float* __restrict__ als0, float* __restrict__ als1,
              float* __restrict__ als2, float* __restrict__ ald2o) {
    if (blockIdx.x < 3) {
        __shared__ int warpsums[8];
        __shared__ int carry;
        if (blockIdx.x == 0)      scan_one256(d0, r0, c0, NSP, warpsums, &carry);
        else if (blockIdx.x == 1) scan_one256(d1, r1, c1, NLOC, warpsums, &carry);
        else                      scan_one256(d2, r2, c2, NLOC, warpsums, &carry);
        return;
    }
    int b = blockIdx.x - 3;
    gemm_rel_dispatch(b % NB_GEMM, b / NB_GEMM, hsp, hloc, Wbase, asbase, ad2,
                      PlocA, PspB, PlocC, als0, als1, als2, ald2o);
}

// ---------------- stage C: scatter3 || ald_dot2 ----------------
__global__ void __launch_bounds__(256)
stageC_kernel(const int* __restrict__ e0, const int* __restrict__ e1, const int* __restrict__ e2,
              int* __restrict__ cu0, int* __restrict__ cu1, int* __restrict__ cu2,
              int* __restrict__ cs0, int* __restrict__ cs1, int* __restrict__ cs2,
              const float* __restrict__ hsp, const float* __restrict__ hloc,
              const float* __restrict__ wdl,
              float* __restrict__ ald0, float* __restrict__ ald1) {
    if (blockIdx.x < NB_CNT) {
        int e = blockIdx.x * 256 + threadIdx.x;
        if (e < EOBS) {
            int d = e0[EOBS + e];
            cs0[atomicAdd(&cu0[d], 1)] = e0[e];
            d = e1[EOBS + e];
            cs1[atomicAdd(&cu1[d], 1)] = e1[e];
        }
        if (e < ENEAR) {
            int d = e2[ENEAR + e];
            cs2[atomicAdd(&cu2[d], 1)] = e2[e];
        }
        return;
    }
    int gw = ((blockIdx.x - NB_CNT) * 256 + threadIdx.x) >> 5;
    int lane = threadIdx.x & 31;
    const float* H; const float* wdp; float* ald; int w;
    if (gw < NSP)             { H = hsp;  wdp = wdl;       ald = ald0; w = gw; }
    else if (gw < NSP + NLOC) { H = hloc; wdp = wdl + 512; ald = ald1; w = gw - NSP; }
    else return;
    float4 hv = ((const float4*)H)[(size_t)w * 32 + lane];
    float r[4];
    #pragma unroll
    for (int hh = 0; hh < 4; ++hh) {
        float4 wv = ((const float4*)wdp)[hh * 32 + lane];
        r[hh] = hv.x * wv.x + hv.y * wv.y + hv.z * wv.z + hv.w * wv.w;
    }
    #pragma unroll
    for (int off = 16; off; off >>= 1) {
        #pragma unroll
        for (int hh = 0; hh < 4; ++hh) r[hh] += __shfl_xor_sync(~0u, r[hh], off);
    }
    if (lane < 4) ald[(size_t)w * 4 + lane] = r[lane];
}

// ---------------- fused softmax + aggregate + residual + bias (+relu) ----------------
__device__ __forceinline__ void acc_edge(float q, uint2 raw,
                                         float& den, float& ax, float& ay, float& az, float& aw) {
    float2 f01 = __half22float2(*(__half2*)&raw.x);
    float2 f23 = __half22float2(*(__half2*)&raw.y);
    den += q;
    ax += q * f01.x; ay += q * f01.y; az += q * f23.x; aw += q * f23.y;
}

__device__ __forceinline__ float4 gather_rel(const int* __restrict__ rp, const int* __restrict__ cs,
                                             const float* __restrict__ als, float ad,
                                             const __half* __restrict__ P,
                                             int w, int lane, int h, bool self) {
    const uint2* P2 = (const uint2*)P;
    float den = 0.f, ax = 0.f, ay = 0.f, az = 0.f, aw = 0.f;
    if (self) {
        float q = __expf(lrelu(__ldg(als + (size_t)w * 4 + h) + ad));
        uint2 raw = __ldg(P2 + (size_t)w * 32 + lane);
        acc_edge(q, raw, den, ax, ay, az, aw);
    }
    int i = __ldg(rp + w), end = __ldg(rp + w + 1);
    for (; i + 4 <= end; i += 4) {
        int s0 = __ldg(cs + i + 0);
        int s1 = __ldg(cs + i + 1);
        int s2 = __ldg(cs + i + 2);
        int s3 = __ldg(cs + i + 3);
        float e0 = lrelu(__ldg(als + (size_t)s0 * 4 + h) + ad);
        float e1 = lrelu(__ldg(als + (size_t)s1 * 4 + h) + ad);
        float e2 = lrelu(__ldg(als + (size_t)s2 * 4 + h) + ad);
        float e3 = lrelu(__ldg(als + (size_t)s3 * 4 + h) + ad);
        uint2 r0 = __ldg(P2 + (size_t)s0 * 32 + lane);
        uint2 r1 = __ldg(P2 + (size_t)s1 * 32 + lane);
        uint2 r2 = __ldg(P2 + (size_t)s2 * 32 + lane);
        uint2 r3 = __ldg(P2 + (size_t)s3 * 32 + lane);
        acc_edge(__expf(e0), r0, den, ax, ay, az, aw);
        acc_edge(__expf(e1), r1, den, ax, ay, az, aw);
        acc_edge(__expf(e2), r2, den, ax, ay, az, aw);
        acc_edge(__expf(e3), r3, den, ax, ay, az, aw);
    }
    for (; i < end; ++i) {
        int s = __ldg(cs + i);
        float q = __expf(lrelu(__ldg(als + (size_t)s * 4 + h) + ad));
        uint2 raw = __ldg(P2 + (size_t)s * 32 + lane);
        acc_edge(q, raw, den, ax, ay, az, aw);
    }
    float inv = 1.f / (den + 1e-16f);
    return make_float4(ax * inv, ay * inv, az * inv, aw * inv);
}

__global__ void aggr_fused_kernel(const int* __restrict__ rp_obs, const int* __restrict__ cs_obs,
                                  const int* __restrict__ rp_obsat, const int* __restrict__ cs_obsat,
                                  const int* __restrict__ rp_near, const int* __restrict__ cs_near,
                                  const float* __restrict__ als0, const float* __restrict__ ald0,
                                  const float* __restrict__ als1, const float* __restrict__ ald1,
                                  const float* __restrict__ als2, const float* __restrict__ ald2,
                                  const __half* __restrict__ PlocA, const __half* __restrict__ PspB,
                                  const __half* __restrict__ PlocC,
                                  const float* __restrict__ hsp, const float* __restrict__ hloc,
                                  const float* __restrict__ b0, const float* __restrict__ b1,
                                  const float* __restrict__ b2,
                                  float* __restrict__ outsp, float* __restrict__ outloc,
                                  int do_relu,
                                  const float* __restrict__ wdn,
                                  float* __restrict__ ald0n, float* __restrict__ ald1n) {
    int gw = (blockIdx.x * blockDim.x + threadIdx.x) >> 5;
    int lane = threadIdx.x & 31;
    int h = lane >> 3;
    float4 o;
    const float* wdsel;
    float* aldout;
    int w;
    if (gw < NSP) {
        w = gw;
        float4 m = gather_rel(rp_obs, cs_obs, als0,
                              __ldg(ald0 + (size_t)w * 4 + h), PlocA, w, lane, h, false);
        float4 hh = __ldg((const float4*)hsp + (size_t)w * 32 + lane);
        float4 bb = __ldg((const float4*)b0 + lane);
        o = make_float4(hh.x + bb.x + m.x, hh.y + bb.y + m.y,
                        hh.z + bb.z + m.z, hh.w + bb.w + m.w);
        if (do_relu) {
            o.x = fmaxf(o.x, 0.f); o.y = fmaxf(o.y, 0.f);
            o.z = fmaxf(o.z, 0.f); o.w = fmaxf(o.w, 0.f);
        }
        ((float4*)outsp)[(size_t)w * 32 + lane] = o;
        wdsel = wdn; aldout = ald0n;
    } else if (gw < NSP + NLOC) {
        w = gw - NSP;
        float4 m1 = gather_rel(rp_obsat, cs_obsat, als1,
                               __ldg(ald1 + (size_t)w * 4 + h), PspB, w, lane, h, false);
        float4 m2 = gather_rel(rp_near, cs_near, als2,
                               __ldg(ald2 + (size_t)w * 4 + h), PlocC, w, lane, h, true);
        float4 hh = ((const float4*)hloc)[(size_t)w * 32 + lane];
        float4 bb1 = __ldg((const float4*)b1 + lane);
        float4 bb2 = __ldg((const float4*)b2 + lane);
        o = make_float4(hh.x + bb1.x + bb2.x + m1.x + m2.x,
                        hh.y + bb1.y + bb2.y + m1.y + m2.y,
                        hh.z + bb1.z + bb2.z + m1.z + m2.z,
                        hh.w + bb1.w + bb2.w + m1.w + m2.w);
        if (do_relu) {
            o.x = fmaxf(o.x, 0.f); o.y = fmaxf(o.y, 0.f);
            o.z = fmaxf(o.z, 0.f); o.w = fmaxf(o.w, 0.f);
        }
        ((float4*)outloc)[(size_t)w * 32 + lane] = o;
        wdsel = wdn ? wdn + 512 : nullptr; aldout = ald1n;
    } else return;

    if (wdn) {
        float r[4];
        #pragma unroll
        for (int hh = 0; hh < 4; ++hh) {
            float4 wv = __ldg((const float4*)wdsel + hh * 32 + lane);
            r[hh] = o.x * wv.x + o.y * wv.y + o.z * wv.z + o.w * wv.w;
        }
        #pragma unroll
        for (int off = 16; off; off >>= 1) {
            #pragma unroll
            for (int hh = 0; hh < 4; ++hh) r[hh] += __shfl_xor_sync(~0u, r[hh], off);
        }
        if (lane < 4) aldout[(size_t)w * 4 + lane] = r[lane];
    }
}

// ---------------- host ----------------
static float* symaddrf(const void* sym) { void* p = nullptr; cudaGetSymbolAddress(&p, sym); return (float*)p; }
static __half* symaddrh(const void* sym) { void* p = nullptr; cudaGetSymbolAddress(&p, sym); return (__half*)p; }
static int*   symaddri(const void* sym) { void* p = nullptr; cudaGetSymbolAddress(&p, sym); return (int*)p; }

extern "C" void kernel_launch(void* const* d_in, const int* in_sizes, int n_in,
                              void* d_out, int out_size) {
    const int*   sp_idx = (const int*)  d_in[0];
    const float* grp    = (const float*)d_in[1];
    const float* locx   = (const float*)d_in[2];
    const int*   ei_obs   = (const int*)d_in[3];
    const int*   ei_obsat = (const int*)d_in[4];
    const int*   ei_near  = (const int*)d_in[5];
    const float* emb    = (const float*)d_in[6];
    const float* spw    = (const float*)d_in[7];
    const float* spb    = (const float*)d_in[8];
    const float* locw   = (const float*)d_in[9];
    const float* locb   = (const float*)d_in[10];
    const float* gatw   = (const float*)d_in[11];
    const float* gatas  = (const float*)d_in[12];
    const float* gatad  = (const float*)d_in[13];
    const float* gatb   = (const float*)d_in[14];
    float* out = (float*)d_out;

    float*  hsp   = symaddrf(g_hsp);
    float*  hloc  = symaddrf(g_hloc);
    __half* PlocA = symaddrh(g_PlocA);
    __half* PlocC = symaddrh(g_PlocC);
    __half* PspB  = symaddrh(g_PspB);
    float* als0  = symaddrf(g_als0);
    float* ald0  = symaddrf(g_ald0);
    float* als1  = symaddrf(g_als1);
    float* ald1  = symaddrf(g_ald1);
    float* als2  = symaddrf(g_als2);
    float* ald2  = symaddrf(g_ald2);
    float* wd    = symaddrf(g_wd);

    int* rp_obs   = symaddri(g_rp_obs);
    int* rp_obsat = symaddri(g_rp_obsat);
    int* rp_near  = symaddri(g_rp_near);
    int* cu_obs   = symaddri(g_cur_obs);
    int* cu_obsat = symaddri(g_cur_obsat);
    int* cu_near  = symaddri(g_cur_near);
    int* dg_obs   = symaddri(g_deg_obs);
    int* dg_obsat = symaddri(g_deg_obsat);
    int* dg_near  = symaddri(g_deg_near);
    int* cs_obs   = symaddri(g_csrc_obs);
    int* cs_obsat = symaddri(g_csrc_obsat);
    int* cs_near  = symaddri(g_csrc_near);

    const float* W0  = gatw;
    const float* as0 = gatas;
    const float* ad2_0 = gatad + 2 * HID;
    const float* b0_0  = gatb;

    // L1: zero degree arrays
    fill3_kernel<<<(NLOC + 255) / 256, 256>>>(dg_obs, NSP, dg_obsat, NLOC, dg_near, NLOC);

    // L2: count || input features || wd
    stageA_kernel<<<NB_CNT + NB_FEAT + NB_G64 + NB_WD, 256>>>(
        ei_obs, ei_obsat, ei_near, dg_obs, dg_obsat, dg_near,
        sp_idx, emb, grp, spw, spb, locx, locw, locb, hsp, hloc,
        gatw, gatad, wd);

    // L3: scan || layer-0 projections+logits
    stageB_kernel<<<3 + 3 * NB_GEMM, 256>>>(
        dg_obs, rp_obs, cu_obs, dg_obsat, rp_obsat, cu_obsat, dg_near, rp_near, cu_near,
        hsp, hloc, W0, as0, ad2_0,
        PlocA, PspB, PlocC, als0, als1, als2, ald2);

    // L4: scatter || layer-0 dst logits
    stageC_kernel<<<NB_CNT + AGGR_BLOCKS, 256>>>(
        ei_obs, ei_obsat, ei_near, cu_obs, cu_obsat, cu_near,
        cs_obs, cs_obsat, cs_near, hsp, hloc, wd, ald0, ald1);

    // L5: layer-0 aggregate (+relu, + next-layer dst logits)
    aggr_fused_kernel<<<AGGR_BLOCKS, 256>>>(
        rp_obs, cs_obs, rp_obsat, cs_obsat, rp_near, cs_near,
        als0, ald0, als1, ald1, als2, ald2,
        PlocA, PspB, PlocC, hsp, hloc,
        b0_0, b0_0 + HID, b0_0 + 2 * HID, hsp, hloc, 1,
        wd + 1024, ald0, ald1);

    // L6: layer-1 projections+logits
    {
        const float* W1l  = gatw  + (size_t)3 * HID * HID;
        const float* as1l = gatas + (size_t)3 * HID;
        const float* ad2_1 = gatad + (size_t)3 * HID + 2 * HID;
        dim3 ggrid(NB_GEMM, 1, 3);
        gemm_tc_fused<<<ggrid, 256>>>(hsp, hloc, W1l, as1l, ad2_1,
                                      PlocA, PspB, PlocC, als0, als1, als2, ald2);
    }

    // L7: layer-1 aggregate -> output
    {
        const float* b0_1 = gatb + (size_t)3 * HID;
        aggr_fused_kernel<<<AGGR_BLOCKS, 256>>>(
            rp_obs, cs_obs, rp_obsat, cs_obsat, rp_near, cs_near,
            als0, ald0, als1, ald1, als2, ald2,
            PlocA, PspB, PlocC, hsp, hloc,
            b0_1, b0_1 + HID, b0_1 + 2 * HID, out, out + (size_t)NSP * HID, 0,
            nullptr, nullptr, nullptr);
    }
}

// round 13
// speedup vs baseline: 1.0935x; 1.0935x over previous
#include <cuda_runtime.h>
#include <cuda_fp16.h>
#include <math.h>
#include <stdint.h>

#define NSP   10000
#define NLOC  50000
#define EOBS  500000
#define ENEAR 400000
#define HID   128
#define HEADS 4
#define CH    32

#define NB_CNT      1954                  // (EOBS+255)/256
#define AGGR_BLOCKS 7500                  // (NSP+NLOC)*32/256

// ---------------- scratch (static device globals) ----------------
__device__ float  g_hsp  [NSP  * HID];
__device__ float  g_hloc [NLOC * HID];
__device__ __half g_PlocA[NLOC * HID];
__device__ __half g_PlocC[NLOC * HID];
__device__ __half g_PspB [NSP  * HID];
__device__ float g_als0[NLOC * HEADS];
__device__ float g_ald0[NSP  * HEADS];
__device__ float g_als1[NSP  * HEADS];
__device__ float g_ald1[NLOC * HEADS];
__device__ float g_als2[NLOC * HEADS];
__device__ float g_ald2[NLOC * HEADS];
__device__ float g_wd  [2 * 2 * HEADS * HID];   // [layer][rel(0=obs,1=obsat)][h][k]

// CSR scratch
__device__ int g_rp_obs  [NSP + 1];
__device__ int g_rp_obsat[NLOC + 1];
__device__ int g_rp_near [NLOC + 1];
__device__ int g_cur_obs  [NSP];
__device__ int g_cur_obsat[NLOC];
__device__ int g_cur_near [NLOC];
__device__ int g_deg_obs  [NSP];
__device__ int g_deg_obsat[NLOC];
__device__ int g_deg_near [NLOC];
__device__ int g_csrc_obs  [EOBS];
__device__ int g_csrc_obsat[EOBS];
__device__ int g_csrc_near [ENEAR];

__device__ __forceinline__ float lrelu(float x) { return x > 0.f ? x : 0.2f * x; }

__device__ __forceinline__ uint32_t f2tf32(float f) {
    uint32_t r;
    asm("cvt.rna.tf32.f32 %0, %1;" : "=r"(r) : "f"(f));
    return r;
}

// ---------------- tf32 GEMM + attention-logit epilogue; P stored as fp16 ----------------
#define WPAD 136
__global__ void __launch_bounds__(256)
gemm_tc_fused(const float* __restrict__ hsp, const float* __restrict__ hloc,
              const float* __restrict__ Wbase, const float* __restrict__ asbase,
              const float* __restrict__ ad2,
              __half* __restrict__ PlocA, __half* __restrict__ PspB, __half* __restrict__ PlocC,
              float* __restrict__ als0, float* __restrict__ als1,
              float* __restrict__ als2, float* __restrict__ ald2o) {
    int rel = blockIdx.z;
    const float* A;  const float* W;  const float* avs;  const float* avd = nullptr;
    __half* C;  float* als;  float* ald = nullptr;  int M;
    if (rel == 0)      { A = hloc; W = Wbase;                C = PlocA; M = NLOC; avs = asbase;           als = als0; }
    else if (rel == 1) { A = hsp;  W = Wbase + HID * HID;    C = PspB;  M = NSP;  avs = asbase + HID;     als = als1; }
    else               { A = hloc; W = Wbase + 2 * HID * HID;C = PlocC; M = NLOC; avs = asbase + 2 * HID; als = als2;
                         avd = ad2; ald = ald2o; }
    if (blockIdx.x * 128 >= M) return;

    __shared__ __align__(16) uint32_t Ws[64 * WPAD];
    int warp = threadIdx.x >> 5, lane = threadIdx.x & 31;
    int gid = lane >> 2, tig = lane & 3;
    int ra = blockIdx.x * 128 + warp * 16 + gid;
    int rb = ra + 8;
    bool va = ra < M, vb = rb < M;
    const float* Aa = A + (size_t)(va ? ra : 0) * HID;
    const float* Ab = A + (size_t)(vb ? rb : 0) * HID;

    float c[16][4];
    #pragma unroll
    for (int t = 0; t < 16; ++t) { c[t][0] = c[t][1] = c[t][2] = c[t][3] = 0.f; }

    for (int kc = 0; kc < 2; ++kc) {
        int kbase = kc * 64;
        __syncthreads();
        // vectorized W staging: float4 load -> 4x cvt -> uint4 store (Ws is 16B-aligned;
        // offset k*WPAD+n4*4 in 4B units = k*544 + n4*16 bytes, both 16B multiples)
        for (int i = threadIdx.x; i < 64 * 32; i += 256) {
            int k = i >> 5, n4 = i & 31;
            float4 w4 = ((const float4*)(W + (size_t)(kbase + k) * HID))[n4];
            uint4 u = make_uint4(f2tf32(w4.x), f2tf32(w4.y), f2tf32(w4.z), f2tf32(w4.w));
            *(uint4*)&Ws[k * WPAD + n4 * 4] = u;
        }
        __syncthreads();
        #pragma unroll
        for (int k8 = 0; k8 < 8; ++k8) {
            int k0 = kbase + k8 * 8;
            int ks = k8 * 8;
            uint32_t a0 = f2tf32(Aa[k0 + tig]);
            uint32_t a1 = f2tf32(Ab[k0 + tig]);
            uint32_t a2 = f2tf32(Aa[k0 + 4 + tig]);
            uint32_t a3 = f2tf32(Ab[k0 + 4 + tig]);
            const uint32_t* b0row = Ws + (ks + tig) * WPAD + gid;
            const uint32_t* b1row = Ws + (ks + 4 + tig) * WPAD + gid;
            #pragma unroll
            for (int t = 0; t < 16; ++t) {
                uint32_t b0 = b0row[t * 8];
                uint32_t b1 = b1row[t * 8];
                asm volatile(
                    "mma.sync.aligned.m16n8k8.row.col.f32.tf32.tf32.f32 "
                    "{%0,%1,%2,%3}, {%4,%5,%6,%7}, {%8,%9}, {%0,%1,%2,%3};"
                    : "+f"(c[t][0]), "+f"(c[t][1]), "+f"(c[t][2]), "+f"(c[t][3])
                    : "r"(a0), "r"(a1), "r"(a2), "r"(a3), "r"(b0), "r"(b1));
            }
        }
    }

    // store projected rows as fp16
    #pragma unroll
    for (int t = 0; t < 16; ++t) {
        int col = t * 8 + 2 * tig;
        if (va) *(__half2*)(C + (size_t)ra * HID + col) = __floats2half2_rn(c[t][0], c[t][1]);
        if (vb) *(__half2*)(C + (size_t)rb * HID + col) = __floats2half2_rn(c[t][2], c[t][3]);
    }

    // epilogue: attention logits via quad reduction (fp32 accumulators)
    {
        float pa[4] = {0, 0, 0, 0}, pb[4] = {0, 0, 0, 0};
        #pragma unroll
        for (int t = 0; t < 16; ++t) {
            int col = t * 8 + 2 * tig;
            float w0 = avs[col], w1 = avs[col + 1];
            pa[t >> 2] += c[t][0] * w0 + c[t][1] * w1;
            pb[t >> 2] += c[t][2] * w0 + c[t][3] * w1;
        }
        #pragma unroll
        for (int hh = 0; hh < 4; ++hh) {
            pa[hh] += __shfl_xor_sync(~0u, pa[hh], 1);
            pa[hh] += __shfl_xor_sync(~0u, pa[hh], 2);
            pb[hh] += __shfl_xor_sync(~0u, pb[hh], 1);
            pb[hh] += __shfl_xor_sync(~0u, pb[hh], 2);
        }
        if (tig == 0) {
            if (va) ((float4*)als)[ra] = make_float4(pa[0], pa[1], pa[2], pa[3]);
            if (vb) ((float4*)als)[rb] = make_float4(pb[0], pb[1], pb[2], pb[3]);
        }
        if (avd) {
            float qa[4] = {0, 0, 0, 0}, qb[4] = {0, 0, 0, 0};
            #pragma unroll
            for (int t = 0; t < 16; ++t) {
                int col = t * 8 + 2 * tig;
                float w0 = avd[col], w1 = avd[col + 1];
                qa[t >> 2] += c[t][0] * w0 + c[t][1] * w1;
                qb[t >> 2] += c[t][2] * w0 + c[t][3] * w1;
            }
            #pragma unroll
            for (int hh = 0; hh < 4; ++hh) {
                qa[hh] += __shfl_xor_sync(~0u, qa[hh], 1);
                qa[hh] += __shfl_xor_sync(~0u, qa[hh], 2);
                qb[hh] += __shfl_xor_sync(~0u, qb[hh], 1);
                qb[hh] += __shfl_xor_sync(~0u, qb[hh], 2);
            }
            if (tig == 0) {
                if (va) ((float4*)ald)[ra] = make_float4(qa[0], qa[1], qa[2], qa[3]);
                if (vb) ((float4*)ald)[rb] = make_float4(qb[0], qb[1], qb[2], qb[3]);
            }
        }
    }
}

// ---------------- input features ----------------
__global__ void gemm64_kernel(const float* __restrict__ A, const float* __restrict__ W,
                              const float* __restrict__ b, float* __restrict__ C, int M) {
    __shared__ __align__(16) float As[16][64];
    int row0 = blockIdx.x * 16;
    int j = threadIdx.x;
    for (int i = j; i < 16 * 64; i += 128) {
        int r = i >> 6, k = i & 63;
        int m = row0 + r;
        As[r][k] = (m < M) ? A[(size_t)m * 64 + k] : 0.f;
    }
    __syncthreads();
    float acc[16];
    #pragma unroll
    for (int r = 0; r < 16; ++r) acc[r] = 0.f;
    const float4* As4 = (const float4*)&As[0][0];
    #pragma unroll 4
    for (int k4 = 0; k4 < 16; ++k4) {
        int k = k4 * 4;
        float w0 = W[(k + 0) * HID + j];
        float w1 = W[(k + 1) * HID + j];
        float w2 = W[(k + 2) * HID + j];
        float w3 = W[(k + 3) * HID + j];
        #pragma unroll
        for (int r = 0; r < 16; ++r) {
            float4 a = As4[r * 16 + k4];
            acc[r] += a.x * w0 + a.y * w1 + a.z * w2 + a.w * w3;
        }
    }
    float bj = b[j];
    #pragma unroll
    for (int r = 0; r < 16; ++r) {
        int m = row0 + r;
        if (m < M) C[(size_t)m * HID + j] = acc[r] + bj;
    }
}

__global__ void feat_sp_kernel(const int* __restrict__ sp_idx,
                               const float* __restrict__ emb, const float* __restrict__ grp,
                               const float* __restrict__ W, const float* __restrict__ b,
                               float* __restrict__ C) {
    __shared__ __align__(16) float As[16][64];
    int row0 = blockIdx.x * 16;
    int j = threadIdx.x;
    for (int i = j; i < 16 * 64; i += 128) {
        int r = i >> 6, k = i & 63;
        int m = row0 + r;
        float v = 0.f;
        if (m < NSP) {
            if (k < 48) v = emb[(size_t)sp_idx[m] * 48 + k];
            else        v = grp[(size_t)m * 16 + (k - 48)];
        }
        As[r][k] = v;
    }
    __syncthreads();
    float acc[16];
    #pragma unroll
    for (int r = 0; r < 16; ++r) acc[r] = 0.f;
    const float4* As4 = (const float4*)&As[0][0];
    #pragma unroll 4
    for (int k4 = 0; k4 < 16; ++k4) {
        int k = k4 * 4;
        float w0 = W[(k + 0) * HID + j];
        float w1 = W[(k + 1) * HID + j];
        float w2 = W[(k + 2) * HID + j];
        float w3 = W[(k + 3) * HID + j];
        #pragma unroll
        for (int r = 0; r < 16; ++r) {
            float4 a = As4[r * 16 + k4];
            acc[r] += a.x * w0 + a.y * w1 + a.z * w2 + a.w * w3;
        }
    }
    float bj = b[j];
    #pragma unroll
    for (int r = 0; r < 16; ++r) {
        int m = row0 + r;
        if (m < NSP) C[(size_t)m * HID + j] = acc[r] + bj;
    }
}

// ---------------- wd (both layers, rels 0/1) ----------------
__global__ void wd_all_kernel(const float* __restrict__ gatw, const float* __restrict__ gatad,
                              float* __restrict__ wd) {
    int t = blockIdx.x * blockDim.x + threadIdx.x;
    if (t >= 2048) return;
    int l = t >> 10, rem = t & 1023, r = rem >> 9, rem2 = rem & 511, h = rem2 >> 7, k = rem2 & 127;
    const float* W  = gatw  + ((size_t)l * 3 + r) * HID * HID;
    const float* ad = gatad + ((size_t)l * 3 + r) * HID;
    float s = 0.f;
    #pragma unroll
    for (int c = 0; c < 32; ++c) s += W[k * HID + h * CH + c] * ad[h * CH + c];
    wd[t] = s;
}

// ---------------- CSR build ----------------
__global__ void fill3_kernel(int* __restrict__ p0, int n0, int* __restrict__ p1, int n1,
                             int* __restrict__ p2, int n2) {
    int i = blockIdx.x * blockDim.x + threadIdx.x;
    if (i < n0) p0[i] = 0;
    if (i < n1) p1[i] = 0;
    if (i < n2) p2[i] = 0;
}

__global__ void count3_kernel(const int* __restrict__ e0, const int* __restrict__ e1,
                              const int* __restrict__ e2,
                              int* __restrict__ d0, int* __restrict__ d1, int* __restrict__ d2) {
    int e = blockIdx.x * blockDim.x + threadIdx.x;
    if (e < EOBS) {
        atomicAdd(&d0[e0[EOBS + e]], 1);
        atomicAdd(&d1[e1[EOBS + e]], 1);
    }
    if (e < ENEAR) atomicAdd(&d2[e2[ENEAR + e]], 1);
}

// warp-shuffle scan: 1024 threads, 4 syncs per 1024-chunk
__device__ void scan_one(const int* __restrict__ deg, int* __restrict__ rowptr,
                         int* __restrict__ cursor, int n, int* warpsums, int* carry_p) {
    int lane = threadIdx.x & 31, wid = threadIdx.x >> 5;
    if (threadIdx.x == 0) *carry_p = 0;
    __syncthreads();
    for (int base = 0; base < n; base += 1024) {
        int i = base + (int)threadIdx.x;
        int v = (i < n) ? deg[i] : 0;
        int x = v;
        #pragma unroll
        for (int off = 1; off < 32; off <<= 1) {
            int t = __shfl_up_sync(~0u, x, off);
            if (lane >= off) x += t;
        }
        if (lane == 31) warpsums[wid] = x;
        __syncthreads();
        if (wid == 0) {
            int s = warpsums[lane];
            #pragma unroll
            for (int off = 1; off < 32; off <<= 1) {
                int t = __shfl_up_sync(~0u, s, off);
                if (lane >= off) s += t;
            }
            warpsums[lane] = s;
        }
        __syncthreads();
        int warpoff = wid ? warpsums[wid - 1] : 0;
        int excl = x - v + warpoff;
        int carry = *carry_p;
        if (i < n) {
            int o = carry + excl;
            rowptr[i] = o;
            cursor[i] = o;
        }
        __syncthreads();
        if (threadIdx.x == 0) *carry_p = carry + warpsums[31];
        __syncthreads();
    }
    if (threadIdx.x == 0) rowptr[n] = *carry_p;
}

__global__ void scan3_kernel(const int* __restrict__ d0, int* __restrict__ r0, int* __restrict__ c0, int n0,
                             const int* __restrict__ d1, int* __restrict__ r1, int* __restrict__ c1, int n1,
                             const int* __restrict__ d2, int* __restrict__ r2, int* __restrict__ c2, int n2) {
    __shared__ int warpsums[32];
    __shared__ int carry;
    if (blockIdx.x == 0)      scan_one(d0, r0, c0, n0, warpsums, &carry);
    else if (blockIdx.x == 1) scan_one(d1, r1, c1, n1, warpsums, &carry);
    else                      scan_one(d2, r2, c2, n2, warpsums, &carry);
}

// ---------------- fused scatter3 + layer-0 dst logits (validated in R12 at 33.8us) ----------------
__global__ void __launch_bounds__(256)
scatter_ald_kernel(const int* __restrict__ e0, const int* __restrict__ e1, const int* __restrict__ e2,
                   int* __restrict__ cu0, int* __restrict__ cu1, int* __restrict__ cu2,
                   int* __restrict__ cs0, int* __restrict__ cs1, int* __restrict__ cs2,
                   const float* __restrict__ hsp, const float* __restrict__ hloc,
                   const float* __restrict__ wdl,
                   float* __restrict__ ald0, float* __restrict__ ald1) {
    if (blockIdx.x < NB_CNT) {
        int e = blockIdx.x * 256 + threadIdx.x;
        if (e < EOBS) {
            int d = e0[EOBS + e];
            cs0[atomicAdd(&cu0[d], 1)] = e0[e];
            d = e1[EOBS + e];
            cs1[atomicAdd(&cu1[d], 1)] = e1[e];
        }
        if (e < ENEAR) {
            int d = e2[ENEAR + e];
            cs2[atomicAdd(&cu2[d], 1)] = e2[e];
        }
        return;
    }
    int gw = ((blockIdx.x - NB_CNT) * 256 + threadIdx.x) >> 5;
    int lane = threadIdx.x & 31;
    const float* H; const float* wdp; float* ald; int w;
    if (gw < NSP)             { H = hsp;  wdp = wdl;       ald = ald0; w = gw; }
    else if (gw < NSP + NLOC) { H = hloc; wdp = wdl + 512; ald = ald1; w = gw - NSP; }
    else return;
    float4 hv = ((const float4*)H)[(size_t)w * 32 + lane];
    float r[4];
    #pragma unroll
    for (int hh = 0; hh < 4; ++hh) {
        float4 wv = ((const float4*)wdp)[hh * 32 + lane];
        r[hh] = hv.x * wv.x + hv.y * wv.y + hv.z * wv.z + hv.w * wv.w;
    }
    #pragma unroll
    for (int off = 16; off; off >>= 1) {
        #pragma unroll
        for (int hh = 0; hh < 4; ++hh) r[hh] += __shfl_xor_sync(~0u, r[hh], off);
    }
    if (lane < 4) ald[(size_t)w * 4 + lane] = r[lane];
}

// ---------------- fused softmax + aggregate + residual + bias (+relu) ----------------
__device__ __forceinline__ void acc_edge(float q, uint2 raw,
                                         float& den, float& ax, float& ay, float& az, float& aw) {
    float2 f01 = __half22float2(*(__half2*)&raw.x);
    float2 f23 = __half22float2(*(__half2*)&raw.y);
    den += q;
    ax += q * f01.x; ay += q * f01.y; az += q * f23.x; aw += q * f23.y;
}

__device__ __forceinline__ float4 gather_rel(const int* __restrict__ rp, const int* __restrict__ cs,
                                             const float* __restrict__ als, float ad,
                                             const __half* __restrict__ P,
                                             int w, int lane, int h, bool self) {
    const uint2* P2 = (const uint2*)P;
    float den = 0.f, ax = 0.f, ay = 0.f, az = 0.f, aw = 0.f;
    if (self) {
        float q = __expf(lrelu(__ldg(als + (size_t)w * 4 + h) + ad));
        uint2 raw = __ldg(P2 + (size_t)w * 32 + lane);
        acc_edge(q, raw, den, ax, ay, az, aw);
    }
    int i = __ldg(rp + w), end = __ldg(rp + w + 1);
    // 8-wide unroll: 8 independent pointer-chases in flight
    for (; i + 8 <= end; i += 8) {
        int s[8];
        #pragma unroll
        for (int u = 0; u < 8; ++u) s[u] = __ldg(cs + i + u);
        float e[8];
        #pragma unroll
        for (int u = 0; u < 8; ++u)
            e[u] = lrelu(__ldg(als + (size_t)s[u] * 4 + h) + ad);
        uint2 r[8];
        #pragma unroll
        for (int u = 0; u < 8; ++u) r[u] = __ldg(P2 + (size_t)s[u] * 32 + lane);
        #pragma unroll
        for (int u = 0; u < 8; ++u) acc_edge(__expf(e[u]), r[u], den, ax, ay, az, aw);
    }
    for (; i + 4 <= end; i += 4) {
        int s0 = __ldg(cs + i + 0);
        int s1 = __ldg(cs + i + 1);
        int s2 = __ldg(cs + i + 2);
        int s3 = __ldg(cs + i + 3);
        float e0 = lrelu(__ldg(als + (size_t)s0 * 4 + h) + ad);
        float e1 = lrelu(__ldg(als + (size_t)s1 * 4 + h) + ad);
        float e2 = lrelu(__ldg(als + (size_t)s2 * 4 + h) + ad);
        float e3 = lrelu(__ldg(als + (size_t)s3 * 4 + h) + ad);
        uint2 r0 = __ldg(P2 + (size_t)s0 * 32 + lane);
        uint2 r1 = __ldg(P2 + (size_t)s1 * 32 + lane);
        uint2 r2 = __ldg(P2 + (size_t)s2 * 32 + lane);
        uint2 r3 = __ldg(P2 + (size_t)s3 * 32 + lane);
        acc_edge(__expf(e0), r0, den, ax, ay, az, aw);
        acc_edge(__expf(e1), r1, den, ax, ay, az, aw);
        acc_edge(__expf(e2), r2, den, ax, ay, az, aw);
        acc_edge(__expf(e3), r3, den, ax, ay, az, aw);
    }
    for (; i < end; ++i) {
        int s = __ldg(cs + i);
        float q = __expf(lrelu(__ldg(als + (size_t)s * 4 + h) + ad));
        uint2 raw = __ldg(P2 + (size_t)s * 32 + lane);
        acc_edge(q, raw, den, ax, ay, az, aw);
    }
    float inv = 1.f / (den + 1e-16f);
    return make_float4(ax * inv, ay * inv, az * inv, aw * inv);
}

// wdn != nullptr: also compute NEXT layer's dst logits from the output row (in registers)
__global__ void aggr_fused_kernel(const int* __restrict__ rp_obs, const int* __restrict__ cs_obs,
                                  const int* __restrict__ rp_obsat, const int* __restrict__ cs_obsat,
                                  const int* __restrict__ rp_near, const int* __restrict__ cs_near,
                                  const float* __restrict__ als0, const float* __restrict__ ald0,
                                  const float* __restrict__ als1, const float* __restrict__ ald1,
                                  const float* __restrict__ als2, const float* __restrict__ ald2,
                                  const __half* __restrict__ PlocA, const __half* __restrict__ PspB,
                                  const __half* __restrict__ PlocC,
                                  const float* __restrict__ hsp, const float* __restrict__ hloc,
                                  const float* __restrict__ b0, const float* __restrict__ b1,
                                  const float* __restrict__ b2,
                                  float* __restrict__ outsp, float* __restrict__ outloc,
                                  int do_relu,
                                  const float* __restrict__ wdn,
                                  float* __restrict__ ald0n, float* __restrict__ ald1n) {
    int gw = (blockIdx.x * blockDim.x + threadIdx.x) >> 5;
    int lane = threadIdx.x & 31;
    int h = lane >> 3;
    float4 o;
    const float* wdsel;
    float* aldout;
    int w;
    if (gw < NSP) {
        w = gw;
        float4 m = gather_rel(rp_obs, cs_obs, als0,
                              __ldg(ald0 + (size_t)w * 4 + h), PlocA, w, lane, h, false);
        float4 hh = __ldg((const float4*)hsp + (size_t)w * 32 + lane);
        float4 bb = __ldg((const float4*)b0 + lane);
        o = make_float4(hh.x + bb.x + m.x, hh.y + bb.y + m.y,
                        hh.z + bb.z + m.z, hh.w + bb.w + m.w);
        if (do_relu) {
            o.x = fmaxf(o.x, 0.f); o.y = fmaxf(o.y, 0.f);
            o.z = fmaxf(o.z, 0.f); o.w = fmaxf(o.w, 0.f);
        }
        ((float4*)outsp)[(size_t)w * 32 + lane] = o;
        wdsel = wdn; aldout = ald0n;
    } else if (gw < NSP + NLOC) {
        w = gw - NSP;
        float4 m1 = gather_rel(rp_obsat, cs_obsat, als1,
                               __ldg(ald1 + (size_t)w * 4 + h), PspB, w, lane, h, false);
        float4 m2 = gather_rel(rp_near, cs_near, als2,
                               __ldg(ald2 + (size_t)w * 4 + h), PlocC, w, lane, h, true);
        float4 hh = ((const float4*)hloc)[(size_t)w * 32 + lane];
        float4 bb1 = __ldg((const float4*)b1 + lane);
        float4 bb2 = __ldg((const float4*)b2 + lane);
        o = make_float4(hh.x + bb1.x + bb2.x + m1.x + m2.x,
                        hh.y + bb1.y + bb2.y + m1.y + m2.y,
                        hh.z + bb1.z + bb2.z + m1.z + m2.z,
                        hh.w + bb1.w + bb2.w + m1.w + m2.w);
        if (do_relu) {
            o.x = fmaxf(o.x, 0.f); o.y = fmaxf(o.y, 0.f);
            o.z = fmaxf(o.z, 0.f); o.w = fmaxf(o.w, 0.f);
        }
        ((float4*)outloc)[(size_t)w * 32 + lane] = o;
        wdsel = wdn ? wdn + 512 : nullptr; aldout = ald1n;
    } else return;

    if (wdn) {
        float r[4];
        #pragma unroll
        for (int hh = 0; hh < 4; ++hh) {
            float4 wv = __ldg((const float4*)wdsel + hh * 32 + lane);
            r[hh] = o.x * wv.x + o.y * wv.y + o.z * wv.z + o.w * wv.w;
        }
        #pragma unroll
        for (int off = 16; off; off >>= 1) {
            #pragma unroll
            for (int hh = 0; hh < 4; ++hh) r[hh] += __shfl_xor_sync(~0u, r[hh], off);
        }
        if (lane < 4) aldout[(size_t)w * 4 + lane] = r[lane];
    }
}

// ---------------- host ----------------
static float* symaddrf(const void* sym) { void* p = nullptr; cudaGetSymbolAddress(&p, sym); return (float*)p; }
static __half* symaddrh(const void* sym) { void* p = nullptr; cudaGetSymbolAddress(&p, sym); return (__half*)p; }
static int*   symaddri(const void* sym) { void* p = nullptr; cudaGetSymbolAddress(&p, sym); return (int*)p; }

extern "C" void kernel_launch(void* const* d_in, const int* in_sizes, int n_in,
                              void* d_out, int out_size) {
    const int*   sp_idx = (const int*)  d_in[0];
    const float* grp    = (const float*)d_in[1];
    const float* locx   = (const float*)d_in[2];
    const int*   ei_obs   = (const int*)d_in[3];
    const int*   ei_obsat = (const int*)d_in[4];
    const int*   ei_near  = (const int*)d_in[5];
    const float* emb    = (const float*)d_in[6];
    const float* spw    = (const float*)d_in[7];
    const float* spb    = (const float*)d_in[8];
    const float* locw   = (const float*)d_in[9];
    const float* locb   = (const float*)d_in[10];
    const float* gatw   = (const float*)d_in[11];
    const float* gatas  = (const float*)d_in[12];
    const float* gatad  = (const float*)d_in[13];
    const float* gatb   = (const float*)d_in[14];
    float* out = (float*)d_out;

    float*  hsp   = symaddrf(g_hsp);
    float*  hloc  = symaddrf(g_hloc);
    __half* PlocA = symaddrh(g_PlocA);
    __half* PlocC = symaddrh(g_PlocC);
    __half* PspB  = symaddrh(g_PspB);
    float* als0  = symaddrf(g_als0);
    float* ald0  = symaddrf(g_ald0);
    float* als1  = symaddrf(g_als1);
    float* ald1  = symaddrf(g_ald1);
    float* als2  = symaddrf(g_als2);
    float* ald2  = symaddrf(g_ald2);
    float* wd    = symaddrf(g_wd);

    int* rp_obs   = symaddri(g_rp_obs);
    int* rp_obsat = symaddri(g_rp_obsat);
    int* rp_near  = symaddri(g_rp_near);
    int* cu_obs   = symaddri(g_cur_obs);
    int* cu_obsat = symaddri(g_cur_obsat);
    int* cu_near  = symaddri(g_cur_near);
    int* dg_obs   = symaddri(g_deg_obs);
    int* dg_obsat = symaddri(g_deg_obsat);
    int* dg_near  = symaddri(g_deg_near);
    int* cs_obs   = symaddri(g_csrc_obs);
    int* cs_obsat = symaddri(g_csrc_obsat);
    int* cs_near  = symaddri(g_csrc_near);

    // CSR counts + features (features must precede fused scatter+ald)
    fill3_kernel<<<(NLOC + 255) / 256, 256>>>(dg_obs, NSP, dg_obsat, NLOC, dg_near, NLOC);
    count3_kernel<<<(EOBS + 255) / 256, 256>>>(ei_obs, ei_obsat, ei_near,
                                               dg_obs, dg_obsat, dg_near);
    feat_sp_kernel<<<(NSP + 15) / 16, 128>>>(sp_idx, emb, grp, spw, spb, hsp);
    gemm64_kernel<<<(NLOC + 15) / 16, 128>>>(locx, locw, locb, hloc, NLOC);
    wd_all_kernel<<<8, 256>>>(gatw, gatad, wd);
    scan3_kernel<<<3, 1024>>>(dg_obs, rp_obs, cu_obs, NSP,
                              dg_obsat, rp_obsat, cu_obsat, NLOC,
                              dg_near, rp_near, cu_near, NLOC);
    // fused: scatter3 + layer-0 dst logits
    scatter_ald_kernel<<<NB_CNT + AGGR_BLOCKS, 256>>>(
        ei_obs, ei_obsat, ei_near, cu_obs, cu_obsat, cu_near,
        cs_obs, cs_obsat, cs_near, hsp, hloc, wd, ald0, ald1);

    for (int l = 0; l < 2; ++l) {
        const float* Wl  = gatw  + (size_t)l * 3 * HID * HID;
        const float* asl = gatas + (size_t)l * 3 * HID;
        const float* ad2 = gatad + (size_t)l * 3 * HID + 2 * HID;
        const float* b0  = gatb  + (size_t)l * 3 * HID;
        const float* b1  = b0 + HID;
        const float* b2  = b0 + 2 * HID;

        dim3 ggrid((NLOC + 127) / 128, 1, 3);
        gemm_tc_fused<<<ggrid, 256>>>(hsp, hloc, Wl, asl, ad2,
                                      PlocA, PspB, PlocC,
                                      als0, als1, als2, ald2);

        if (l == 0) {
            aggr_fused_kernel<<<AGGR_BLOCKS, 256>>>(rp_obs, cs_obs, rp_obsat, cs_obsat,
                                                    rp_near, cs_near,
                                                    als0, ald0, als1, ald1, als2, ald2,
                                                    PlocA, PspB, PlocC, hsp, hloc,
                                                    b0, b1, b2, hsp, hloc, 1,
                                                    wd + 1024, ald0, ald1);
        } else {
            aggr_fused_kernel<<<AGGR_BLOCKS, 256>>>(rp_obs, cs_obs, rp_obsat, cs_obsat,
                                                    rp_near, cs_near,
                                                    als0, ald0, als1, ald1, als2, ald2,
                                                    PlocA, PspB, PlocC, hsp, hloc,
                                                    b0, b1, b2, out, out + (size_t)NSP * HID, 0,
                                                    nullptr, nullptr, nullptr);
        }
    }
}

// round 14
// speedup vs baseline: 1.1850x; 1.0836x over previous
#include <cuda_runtime.h>
#include <cuda_fp16.h>
#include <math.h>
#include <stdint.h>

#define NSP   10000
#define NLOC  50000
#define EOBS  500000
#define ENEAR 400000
#define HID   128
#define HEADS 4
#define CH    32

#define NB_CNT      1954                  // (EOBS+255)/256
#define AGGR_BLOCKS 7500                  // (NSP+NLOC)*32/256

// ---------------- scratch (static device globals) ----------------
__device__ float  g_hsp  [NSP  * HID];
__device__ float  g_hloc [NLOC * HID];
__device__ float  g_featsp[NSP * 64];
__device__ __half g_PlocA[NLOC * HID];
__device__ __half g_PlocC[NLOC * HID];
__device__ __half g_PspB [NSP  * HID];
__device__ float g_als0[NLOC * HEADS];
__device__ float g_ald0[NSP  * HEADS];
__device__ float g_als1[NSP  * HEADS];
__device__ float g_ald1[NLOC * HEADS];
__device__ float g_als2[NLOC * HEADS];
__device__ float g_ald2[NLOC * HEADS];
__device__ float g_wd  [2 * 2 * HEADS * HID];   // [layer][rel(0=obs,1=obsat)][h][k]

// CSR scratch
__device__ int g_rp_obs  [NSP + 1];
__device__ int g_rp_obsat[NLOC + 1];
__device__ int g_rp_near [NLOC + 1];
__device__ int g_cur_obs  [NSP];
__device__ int g_cur_obsat[NLOC];
__device__ int g_cur_near [NLOC];
__device__ int g_deg_obs  [NSP];
__device__ int g_deg_obsat[NLOC];
__device__ int g_deg_near [NLOC];
__device__ int g_csrc_obs  [EOBS];
__device__ int g_csrc_obsat[EOBS];
__device__ int g_csrc_near [ENEAR];

__device__ __forceinline__ float lrelu(float x) { return x > 0.f ? x : 0.2f * x; }

__device__ __forceinline__ uint32_t f2tf32(float f) {
    uint32_t r;
    asm("cvt.rna.tf32.f32 %0, %1;" : "=r"(r) : "f"(f));
    return r;
}

#define WPAD 136

// ---------------- tf32 GEMM + attention-logit epilogue; P stored as fp16 ----------------
__global__ void __launch_bounds__(256)
gemm_tc_fused(const float* __restrict__ hsp, const float* __restrict__ hloc,
              const float* __restrict__ Wbase, const float* __restrict__ asbase,
              const float* __restrict__ ad2,
              __half* __restrict__ PlocA, __half* __restrict__ PspB, __half* __restrict__ PlocC,
              float* __restrict__ als0, float* __restrict__ als1,
              float* __restrict__ als2, float* __restrict__ ald2o) {
    int rel = blockIdx.z;
    const float* A;  const float* W;  const float* avs;  const float* avd = nullptr;
    __half* C;  float* als;  float* ald = nullptr;  int M;
    if (rel == 0)      { A = hloc; W = Wbase;                C = PlocA; M = NLOC; avs = asbase;           als = als0; }
    else if (rel == 1) { A = hsp;  W = Wbase + HID * HID;    C = PspB;  M = NSP;  avs = asbase + HID;     als = als1; }
    else               { A = hloc; W = Wbase + 2 * HID * HID;C = PlocC; M = NLOC; avs = asbase + 2 * HID; als = als2;
                         avd = ad2; ald = ald2o; }
    if (blockIdx.x * 128 >= M) return;

    __shared__ __align__(16) uint32_t Ws[64 * WPAD];
    int warp = threadIdx.x >> 5, lane = threadIdx.x & 31;
    int gid = lane >> 2, tig = lane & 3;
    int ra = blockIdx.x * 128 + warp * 16 + gid;
    int rb = ra + 8;
    bool va = ra < M, vb = rb < M;
    const float* Aa = A + (size_t)(va ? ra : 0) * HID;
    const float* Ab = A + (size_t)(vb ? rb : 0) * HID;

    float c[16][4];
    #pragma unroll
    for (int t = 0; t < 16; ++t) { c[t][0] = c[t][1] = c[t][2] = c[t][3] = 0.f; }

    for (int kc = 0; kc < 2; ++kc) {
        int kbase = kc * 64;
        __syncthreads();
        for (int i = threadIdx.x; i < 64 * 32; i += 256) {
            int k = i >> 5, n4 = i & 31;
            float4 w4 = ((const float4*)(W + (size_t)(kbase + k) * HID))[n4];
            uint4 u = make_uint4(f2tf32(w4.x), f2tf32(w4.y), f2tf32(w4.z), f2tf32(w4.w));
            *(uint4*)&Ws[k * WPAD + n4 * 4] = u;
        }
        __syncthreads();
        #pragma unroll
        for (int k8 = 0; k8 < 8; ++k8) {
            int k0 = kbase + k8 * 8;
            int ks = k8 * 8;
            uint32_t a0 = f2tf32(Aa[k0 + tig]);
            uint32_t a1 = f2tf32(Ab[k0 + tig]);
            uint32_t a2 = f2tf32(Aa[k0 + 4 + tig]);
            uint32_t a3 = f2tf32(Ab[k0 + 4 + tig]);
            const uint32_t* b0row = Ws + (ks + tig) * WPAD + gid;
            const uint32_t* b1row = Ws + (ks + 4 + tig) * WPAD + gid;
            #pragma unroll
            for (int t = 0; t < 16; ++t) {
                uint32_t b0 = b0row[t * 8];
                uint32_t b1 = b1row[t * 8];
                asm volatile(
                    "mma.sync.aligned.m16n8k8.row.col.f32.tf32.tf32.f32 "
                    "{%0,%1,%2,%3}, {%4,%5,%6,%7}, {%8,%9}, {%0,%1,%2,%3};"
                    : "+f"(c[t][0]), "+f"(c[t][1]), "+f"(c[t][2]), "+f"(c[t][3])
                    : "r"(a0), "r"(a1), "r"(a2), "r"(a3), "r"(b0), "r"(b1));
            }
        }
    }

    #pragma unroll
    for (int t = 0; t < 16; ++t) {
        int col = t * 8 + 2 * tig;
        if (va) *(__half2*)(C + (size_t)ra * HID + col) = __floats2half2_rn(c[t][0], c[t][1]);
        if (vb) *(__half2*)(C + (size_t)rb * HID + col) = __floats2half2_rn(c[t][2], c[t][3]);
    }

    {
        float pa[4] = {0, 0, 0, 0}, pb[4] = {0, 0, 0, 0};
        #pragma unroll
        for (int t = 0; t < 16; ++t) {
            int col = t * 8 + 2 * tig;
            float w0 = avs[col], w1 = avs[col + 1];
            pa[t >> 2] += c[t][0] * w0 + c[t][1] * w1;
            pb[t >> 2] += c[t][2] * w0 + c[t][3] * w1;
        }
        #pragma unroll
        for (int hh = 0; hh < 4; ++hh) {
            pa[hh] += __shfl_xor_sync(~0u, pa[hh], 1);
            pa[hh] += __shfl_xor_sync(~0u, pa[hh], 2);
            pb[hh] += __shfl_xor_sync(~0u, pb[hh], 1);
            pb[hh] += __shfl_xor_sync(~0u, pb[hh], 2);
        }
        if (tig == 0) {
            if (va) ((float4*)als)[ra] = make_float4(pa[0], pa[1], pa[2], pa[3]);
            if (vb) ((float4*)als)[rb] = make_float4(pb[0], pb[1], pb[2], pb[3]);
        }
        if (avd) {
            float qa[4] = {0, 0, 0, 0}, qb[4] = {0, 0, 0, 0};
            #pragma unroll
            for (int t = 0; t < 16; ++t) {
                int col = t * 8 + 2 * tig;
                float w0 = avd[col], w1 = avd[col + 1];
                qa[t >> 2] += c[t][0] * w0 + c[t][1] * w1;
                qb[t >> 2] += c[t][2] * w0 + c[t][3] * w1;
            }
            #pragma unroll
            for (int hh = 0; hh < 4; ++hh) {
                qa[hh] += __shfl_xor_sync(~0u, qa[hh], 1);
                qa[hh] += __shfl_xor_sync(~0u, qa[hh], 2);
                qb[hh] += __shfl_xor_sync(~0u, qb[hh], 1);
                qb[hh] += __shfl_xor_sync(~0u, qb[hh], 2);
            }
            if (tig == 0) {
                if (va) ((float4*)ald)[ra] = make_float4(qa[0], qa[1], qa[2], qa[3]);
                if (vb) ((float4*)ald)[rb] = make_float4(qb[0], qb[1], qb[2], qb[3]);
            }
        }
    }
}

// ---------------- input projection on tensor cores: C[M,128] = A[M,64]@W[64,128] + b ----------------
// grid.z: 0 = locations (locx), 1 = species (featsp)
__global__ void __launch_bounds__(256)
gemm_in_kernel(const float* __restrict__ locx, const float* __restrict__ featsp,
               const float* __restrict__ locw, const float* __restrict__ locb,
               const float* __restrict__ spw, const float* __restrict__ spb,
               float* __restrict__ hloc, float* __restrict__ hsp) {
    const float* A; const float* W; const float* b; float* C; int M;
    if (blockIdx.z == 0) { A = locx;   W = locw; b = locb; C = hloc; M = NLOC; }
    else                 { A = featsp; W = spw;  b = spb;  C = hsp;  M = NSP;  }
    if (blockIdx.x * 128 >= M) return;

    __shared__ __align__(16) uint32_t Ws[64 * WPAD];
    int warp = threadIdx.x >> 5, lane = threadIdx.x & 31;
    int gid = lane >> 2, tig = lane & 3;
    int ra = blockIdx.x * 128 + warp * 16 + gid;
    int rb = ra + 8;
    bool va = ra < M, vb = rb < M;
    const float* Aa = A + (size_t)(va ? ra : 0) * 64;
    const float* Ab = A + (size_t)(vb ? rb : 0) * 64;

    // stage W (64x128) once
    for (int i = threadIdx.x; i < 64 * 32; i += 256) {
        int k = i >> 5, n4 = i & 31;
        float4 w4 = ((const float4*)(W + (size_t)k * HID))[n4];
        uint4 u = make_uint4(f2tf32(w4.x), f2tf32(w4.y), f2tf32(w4.z), f2tf32(w4.w));
        *(uint4*)&Ws[k * WPAD + n4 * 4] = u;
    }
    __syncthreads();

    float c[16][4];
    #pragma unroll
    for (int t = 0; t < 16; ++t) { c[t][0] = c[t][1] = c[t][2] = c[t][3] = 0.f; }

    #pragma unroll
    for (int k8 = 0; k8 < 8; ++k8) {
        int k0 = k8 * 8;
        uint32_t a0 = f2tf32(Aa[k0 + tig]);
        uint32_t a1 = f2tf32(Ab[k0 + tig]);
        uint32_t a2 = f2tf32(Aa[k0 + 4 + tig]);
        uint32_t a3 = f2tf32(Ab[k0 + 4 + tig]);
        const uint32_t* b0row = Ws + (k0 + tig) * WPAD + gid;
        const uint32_t* b1row = Ws + (k0 + 4 + tig) * WPAD + gid;
        #pragma unroll
        for (int t = 0; t < 16; ++t) {
            uint32_t b0 = b0row[t * 8];
            uint32_t b1 = b1row[t * 8];
            asm volatile(
                "mma.sync.aligned.m16n8k8.row.col.f32.tf32.tf32.f32 "
                "{%0,%1,%2,%3}, {%4,%5,%6,%7}, {%8,%9}, {%0,%1,%2,%3};"
                : "+f"(c[t][0]), "+f"(c[t][1]), "+f"(c[t][2]), "+f"(c[t][3])
                : "r"(a0), "r"(a1), "r"(a2), "r"(a3), "r"(b0), "r"(b1));
        }
    }

    #pragma unroll
    for (int t = 0; t < 16; ++t) {
        int col = t * 8 + 2 * tig;
        float2 bv = *(const float2*)(b + col);
        if (va) *(float2*)(C + (size_t)ra * HID + col) =
            make_float2(c[t][0] + bv.x, c[t][1] + bv.y);
        if (vb) *(float2*)(C + (size_t)rb * HID + col) =
            make_float2(c[t][2] + bv.x, c[t][3] + bv.y);
    }
}

// species feature gather: featsp[m][k] = k<48 ? emb[sp_idx[m]][k] : grp[m][k-48]
__global__ void featgather_kernel(const int* __restrict__ sp_idx,
                                  const float* __restrict__ emb, const float* __restrict__ grp,
                                  float* __restrict__ featsp) {
    int i = blockIdx.x * blockDim.x + threadIdx.x;
    if (i >= NSP * 64) return;
    int m = i >> 6, k = i & 63;
    float v;
    if (k < 48) v = emb[(size_t)sp_idx[m] * 48 + k];
    else        v = grp[(size_t)m * 16 + (k - 48)];
    featsp[i] = v;
}

// ---------------- wd (both layers, rels 0/1) ----------------
__global__ void wd_all_kernel(const float* __restrict__ gatw, const float* __restrict__ gatad,
                              float* __restrict__ wd) {
    int t = blockIdx.x * blockDim.x + threadIdx.x;
    if (t >= 2048) return;
    int l = t >> 10, rem = t & 1023, r = rem >> 9, rem2 = rem & 511, h = rem2 >> 7, k = rem2 & 127;
    const float* W  = gatw  + ((size_t)l * 3 + r) * HID * HID;
    const float* ad = gatad + ((size_t)l * 3 + r) * HID;
    float s = 0.f;
    #pragma unroll
    for (int c = 0; c < 32; ++c) s += W[k * HID + h * CH + c] * ad[h * CH + c];
    wd[t] = s;
}

// ---------------- CSR build ----------------
__global__ void fill3_kernel(int* __restrict__ p0, int n0, int* __restrict__ p1, int n1,
                             int* __restrict__ p2, int n2) {
    int i = blockIdx.x * blockDim.x + threadIdx.x;
    if (i < n0) p0[i] = 0;
    if (i < n1) p1[i] = 0;
    if (i < n2) p2[i] = 0;
}

__global__ void count3_kernel(const int* __restrict__ e0, const int* __restrict__ e1,
                              const int* __restrict__ e2,
                              int* __restrict__ d0, int* __restrict__ d1, int* __restrict__ d2) {
    int e = blockIdx.x * blockDim.x + threadIdx.x;
    if (e < EOBS) {
        atomicAdd(&d0[e0[EOBS + e]], 1);
        atomicAdd(&d1[e1[EOBS + e]], 1);
    }
    if (e < ENEAR) atomicAdd(&d2[e2[ENEAR + e]], 1);
}

// warp-shuffle scan: 1024 threads, 4 syncs per 1024-chunk
__device__ void scan_one(const int* __restrict__ deg, int* __restrict__ rowptr,
                         int* __restrict__ cursor, int n, int* warpsums, int* carry_p) {
    int lane = threadIdx.x & 31, wid = threadIdx.x >> 5;
    if (threadIdx.x == 0) *carry_p = 0;
    __syncthreads();
    for (int base = 0; base < n; base += 1024) {
        int i = base + (int)threadIdx.x;
        int v = (i < n) ? deg[i] : 0;
        int x = v;
        #pragma unroll
        for (int off = 1; off < 32; off <<= 1) {
            int t = __shfl_up_sync(~0u, x, off);
            if (lane >= off) x += t;
        }
        if (lane == 31) warpsums[wid] = x;
        __syncthreads();
        if (wid == 0) {
            int s = warpsums[lane];
            #pragma unroll
            for (int off = 1; off < 32; off <<= 1) {
                int t = __shfl_up_sync(~0u, s, off);
                if (lane >= off) s += t;
            }
            warpsums[lane] = s;
        }
        __syncthreads();
        int warpoff = wid ? warpsums[wid - 1] : 0;
        int excl = x - v + warpoff;
        int carry = *carry_p;
        if (i < n) {
            int o = carry + excl;
            rowptr[i] = o;
            cursor[i] = o;
        }
        __syncthreads();
        if (threadIdx.x == 0) *carry_p = carry + warpsums[31];
        __syncthreads();
    }
    if (threadIdx.x == 0) rowptr[n] = *carry_p;
}

__global__ void scan3_kernel(const int* __restrict__ d0, int* __restrict__ r0, int* __restrict__ c0, int n0,
                             const int* __restrict__ d1, int* __restrict__ r1, int* __restrict__ c1, int n1,
                             const int* __restrict__ d2, int* __restrict__ r2, int* __restrict__ c2, int n2) {
    __shared__ int warpsums[32];
    __shared__ int carry;
    if (blockIdx.x == 0)      scan_one(d0, r0, c0, n0, warpsums, &carry);
    else if (blockIdx.x == 1) scan_one(d1, r1, c1, n1, warpsums, &carry);
    else                      scan_one(d2, r2, c2, n2, warpsums, &carry);
}

// ---------------- fused scatter3 + layer-0 dst logits ----------------
__global__ void __launch_bounds__(256)
scatter_ald_kernel(const int* __restrict__ e0, const int* __restrict__ e1, const int* __restrict__ e2,
                   int* __restrict__ cu0, int* __restrict__ cu1, int* __restrict__ cu2,
                   int* __restrict__ cs0, int* __restrict__ cs1, int* __restrict__ cs2,
                   const float* __restrict__ hsp, const float* __restrict__ hloc,
                   const float* __restrict__ wdl,
                   float* __restrict__ ald0, float* __restrict__ ald1) {
    if (blockIdx.x < NB_CNT) {
        int e = blockIdx.x * 256 + threadIdx.x;
        if (e < EOBS) {
            int d = e0[EOBS + e];
            cs0[atomicAdd(&cu0[d], 1)] = e0[e];
            d = e1[EOBS + e];
            cs1[atomicAdd(&cu1[d], 1)] = e1[e];
        }
        if (e < ENEAR) {
            int d = e2[ENEAR + e];
            cs2[atomicAdd(&cu2[d], 1)] = e2[e];
        }
        return;
    }
    int gw = ((blockIdx.x - NB_CNT) * 256 + threadIdx.x) >> 5;
    int lane = threadIdx.x & 31;
    const float* H; const float* wdp; float* ald; int w;
    if (gw < NSP)             { H = hsp;  wdp = wdl;       ald = ald0; w = gw; }
    else if (gw < NSP + NLOC) { H = hloc; wdp = wdl + 512; ald = ald1; w = gw - NSP; }
    else return;
    float4 hv = ((const float4*)H)[(size_t)w * 32 + lane];
    float r[4];
    #pragma unroll
    for (int hh = 0; hh < 4; ++hh) {
        float4 wv = ((const float4*)wdp)[hh * 32 + lane];
        r[hh] = hv.x * wv.x + hv.y * wv.y + hv.z * wv.z + hv.w * wv.w;
    }
    #pragma unroll
    for (int off = 16; off; off >>= 1) {
        #pragma unroll
        for (int hh = 0; hh < 4; ++hh) r[hh] += __shfl_xor_sync(~0u, r[hh], off);
    }
    if (lane < 4) ald[(size_t)w * 4 + lane] = r[lane];
}

// ---------------- fused softmax + aggregate + residual + bias (+relu) ----------------
__device__ __forceinline__ void acc_edge(float q, uint2 raw,
                                         float& den, float& ax, float& ay, float& az, float& aw) {
    float2 f01 = __half22float2(*(__half2*)&raw.x);
    float2 f23 = __half22float2(*(__half2*)&raw.y);
    den += q;
    ax += q * f01.x; ay += q * f01.y; az += q * f23.x; aw += q * f23.y;
}

__device__ __forceinline__ float4 gather_rel(const int* __restrict__ rp, const int* __restrict__ cs,
                                             const float* __restrict__ als, float ad,
                                             const __half* __restrict__ P,
                                             int w, int lane, int h, bool self) {
    const uint2* P2 = (const uint2*)P;
    float den = 0.f, ax = 0.f, ay = 0.f, az = 0.f, aw = 0.f;
    if (self) {
        float q = __expf(lrelu(__ldg(als + (size_t)w * 4 + h) + ad));
        uint2 raw = __ldg(P2 + (size_t)w * 32 + lane);
        acc_edge(q, raw, den, ax, ay, az, aw);
    }
    int i = __ldg(rp + w), end = __ldg(rp + w + 1);
    for (; i + 8 <= end; i += 8) {
        int s[8];
        #pragma unroll
        for (int u = 0; u < 8; ++u) s[u] = __ldg(cs + i + u);
        float e[8];
        #pragma unroll
        for (int u = 0; u < 8; ++u)
            e[u] = lrelu(__ldg(als + (size_t)s[u] * 4 + h) + ad);
        uint2 r[8];
        #pragma unroll
        for (int u = 0; u < 8; ++u) r[u] = __ldg(P2 + (size_t)s[u] * 32 + lane);
        #pragma unroll
        for (int u = 0; u < 8; ++u) acc_edge(__expf(e[u]), r[u], den, ax, ay, az, aw);
    }
    for (; i + 4 <= end; i += 4) {
        int s0 = __ldg(cs + i + 0);
        int s1 = __ldg(cs + i + 1);
        int s2 = __ldg(cs + i + 2);
        int s3 = __ldg(cs + i + 3);
        float e0 = lrelu(__ldg(als + (size_t)s0 * 4 + h) + ad);
        float e1 = lrelu(__ldg(als + (size_t)s1 * 4 + h) + ad);
        float e2 = lrelu(__ldg(als + (size_t)s2 * 4 + h) + ad);
        float e3 = lrelu(__ldg(als + (size_t)s3 * 4 + h) + ad);
        uint2 r0 = __ldg(P2 + (size_t)s0 * 32 + lane);
        uint2 r1 = __ldg(P2 + (size_t)s1 * 32 + lane);
        uint2 r2 = __ldg(P2 + (size_t)s2 * 32 + lane);
        uint2 r3 = __ldg(P2 + (size_t)s3 * 32 + lane);
        acc_edge(__expf(e0), r0, den, ax, ay, az, aw);
        acc_edge(__expf(e1), r1, den, ax, ay, az, aw);
        acc_edge(__expf(e2), r2, den, ax, ay, az, aw);
        acc_edge(__expf(e3), r3, den, ax, ay, az, aw);
    }
    for (; i < end; ++i) {
        int s = __ldg(cs + i);
        float q = __expf(lrelu(__ldg(als + (size_t)s * 4 + h) + ad));
        uint2 raw = __ldg(P2 + (size_t)s * 32 + lane);
        acc_edge(q, raw, den, ax, ay, az, aw);
    }
    float inv = 1.f / (den + 1e-16f);
    return make_float4(ax * inv, ay * inv, az * inv, aw * inv);
}

__global__ void aggr_fused_kernel(const int* __restrict__ rp_obs, const int* __restrict__ cs_obs,
                                  const int* __restrict__ rp_obsat, const int* __restrict__ cs_obsat,
                                  const int* __restrict__ rp_near, const int* __restrict__ cs_near,
                                  const float* __restrict__ als0, const float* __restrict__ ald0,
                                  const float* __restrict__ als1, const float* __restrict__ ald1,
                                  const float* __restrict__ als2, const float* __restrict__ ald2,
                                  const __half* __restrict__ PlocA, const __half* __restrict__ PspB,
                                  const __half* __restrict__ PlocC,
                                  const float* __restrict__ hsp, const float* __restrict__ hloc,
                                  const float* __restrict__ b0, const float* __restrict__ b1,
                                  const float* __restrict__ b2,
                                  float* __restrict__ outsp, float* __restrict__ outloc,
                                  int do_relu,
                                  const float* __restrict__ wdn,
                                  float* __restrict__ ald0n, float* __restrict__ ald1n) {
    int gw = (blockIdx.x * blockDim.x + threadIdx.x) >> 5;
    int lane = threadIdx.x & 31;
    int h = lane >> 3;
    float4 o;
    const float* wdsel;
    float* aldout;
    int w;
    if (gw < NSP) {
        w = gw;
        float4 m = gather_rel(rp_obs, cs_obs, als0,
                              __ldg(ald0 + (size_t)w * 4 + h), PlocA, w, lane, h, false);
        float4 hh = __ldg((const float4*)hsp + (size_t)w * 32 + lane);
        float4 bb = __ldg((const float4*)b0 + lane);
        o = make_float4(hh.x + bb.x + m.x, hh.y + bb.y + m.y,
                        hh.z + bb.z + m.z, hh.w + bb.w + m.w);
        if (do_relu) {
            o.x = fmaxf(o.x, 0.f); o.y = fmaxf(o.y, 0.f);
            o.z = fmaxf(o.z, 0.f); o.w = fmaxf(o.w, 0.f);
        }
        ((float4*)outsp)[(size_t)w * 32 + lane] = o;
        wdsel = wdn; aldout = ald0n;
    } else if (gw < NSP + NLOC) {
        w = gw - NSP;
        float4 m1 = gather_rel(rp_obsat, cs_obsat, als1,
                               __ldg(ald1 + (size_t)w * 4 + h), PspB, w, lane, h, false);
        float4 m2 = gather_rel(rp_near, cs_near, als2,
                               __ldg(ald2 + (size_t)w * 4 + h), PlocC, w, lane, h, true);
        float4 hh = ((const float4*)hloc)[(size_t)w * 32 + lane];
        float4 bb1 = __ldg((const float4*)b1 + lane);
        float4 bb2 = __ldg((const float4*)b2 + lane);
        o = make_float4(hh.x + bb1.x + bb2.x + m1.x + m2.x,
                        hh.y + bb1.y + bb2.y + m1.y + m2.y,
                        hh.z + bb1.z + bb2.z + m1.z + m2.z,
                        hh.w + bb1.w + bb2.w + m1.w + m2.w);
        if (do_relu) {
            o.x = fmaxf(o.x, 0.f); o.y = fmaxf(o.y, 0.f);
            o.z = fmaxf(o.z, 0.f); o.w = fmaxf(o.w, 0.f);
        }
        ((float4*)outloc)[(size_t)w * 32 + lane] = o;
        wdsel = wdn ? wdn + 512 : nullptr; aldout = ald1n;
    } else return;

    if (wdn) {
        float r[4];
        #pragma unroll
        for (int hh = 0; hh < 4; ++hh) {
            float4 wv = __ldg((const float4*)wdsel + hh * 32 + lane);
            r[hh] = o.x * wv.x + o.y * wv.y + o.z * wv.z + o.w * wv.w;
        }
        #pragma unroll
        for (int off = 16; off; off >>= 1) {
            #pragma unroll
            for (int hh = 0; hh < 4; ++hh) r[hh] += __shfl_xor_sync(~0u, r[hh], off);
        }
        if (lane < 4) aldout[(size_t)w * 4 + lane] = r[lane];
    }
}

// ---------------- host ----------------
static float* symaddrf(const void* sym) { void* p = nullptr; cudaGetSymbolAddress(&p, sym); return (float*)p; }
static __half* symaddrh(const void* sym) { void* p = nullptr; cudaGetSymbolAddress(&p, sym); return (__half*)p; }
static int*   symaddri(const void* sym) { void* p = nullptr; cudaGetSymbolAddress(&p, sym); return (int*)p; }

extern "C" void kernel_launch(void* const* d_in, const int* in_sizes, int n_in,
                              void* d_out, int out_size) {
    const int*   sp_idx = (const int*)  d_in[0];
    const float* grp    = (const float*)d_in[1];
    const float* locx   = (const float*)d_in[2];
    const int*   ei_obs   = (const int*)d_in[3];
    const int*   ei_obsat = (const int*)d_in[4];
    const int*   ei_near  = (const int*)d_in[5];
    const float* emb    = (const float*)d_in[6];
    const float* spw    = (const float*)d_in[7];
    const float* spb    = (const float*)d_in[8];
    const float* locw   = (const float*)d_in[9];
    const float* locb   = (const float*)d_in[10];
    const float* gatw   = (const float*)d_in[11];
    const float* gatas  = (const float*)d_in[12];
    const float* gatad  = (const float*)d_in[13];
    const float* gatb   = (const float*)d_in[14];
    float* out = (float*)d_out;

    float*  hsp   = symaddrf(g_hsp);
    float*  hloc  = symaddrf(g_hloc);
    float*  featsp= symaddrf(g_featsp);
    __half* PlocA = symaddrh(g_PlocA);
    __half* PlocC = symaddrh(g_PlocC);
    __half* PspB  = symaddrh(g_PspB);
    float* als0  = symaddrf(g_als0);
    float* ald0  = symaddrf(g_ald0);
    float* als1  = symaddrf(g_als1);
    float* ald1  = symaddrf(g_ald1);
    float* als2  = symaddrf(g_als2);
    float* ald2  = symaddrf(g_ald2);
    float* wd    = symaddrf(g_wd);

    int* rp_obs   = symaddri(g_rp_obs);
    int* rp_obsat = symaddri(g_rp_obsat);
    int* rp_near  = symaddri(g_rp_near);
    int* cu_obs   = symaddri(g_cur_obs);
    int* cu_obsat = symaddri(g_cur_obsat);
    int* cu_near  = symaddri(g_cur_near);
    int* dg_obs   = symaddri(g_deg_obs);
    int* dg_obsat = symaddri(g_deg_obsat);
    int* dg_near  = symaddri(g_deg_near);
    int* cs_obs   = symaddri(g_csrc_obs);
    int* cs_obsat = symaddri(g_csrc_obsat);
    int* cs_near  = symaddri(g_csrc_near);

    // CSR counts + input features
    fill3_kernel<<<(NLOC + 255) / 256, 256>>>(dg_obs, NSP, dg_obsat, NLOC, dg_near, NLOC);
    count3_kernel<<<(EOBS + 255) / 256, 256>>>(ei_obs, ei_obsat, ei_near,
                                               dg_obs, dg_obsat, dg_near);
    featgather_kernel<<<(NSP * 64 + 255) / 256, 256>>>(sp_idx, emb, grp, featsp);
    {
        dim3 igrid((NLOC + 127) / 128, 1, 2);
        gemm_in_kernel<<<igrid, 256>>>(locx, featsp, locw, locb, spw, spb, hloc, hsp);
    }
    wd_all_kernel<<<8, 256>>>(gatw, gatad, wd);
    scan3_kernel<<<3, 1024>>>(dg_obs, rp_obs, cu_obs, NSP,
                              dg_obsat, rp_obsat, cu_obsat, NLOC,
                              dg_near, rp_near, cu_near, NLOC);
    // fused: scatter3 + layer-0 dst logits
    scatter_ald_kernel<<<NB_CNT + AGGR_BLOCKS, 256>>>(
        ei_obs, ei_obsat, ei_near, cu_obs, cu_obsat, cu_near,
        cs_obs, cs_obsat, cs_near, hsp, hloc, wd, ald0, ald1);

    for (int l = 0; l < 2; ++l) {
        const float* Wl  = gatw  + (size_t)l * 3 * HID * HID;
        const float* asl = gatas + (size_t)l * 3 * HID;
        const float* ad2 = gatad + (size_t)l * 3 * HID + 2 * HID;
        const float* b0  = gatb  + (size_t)l * 3 * HID;
        const float* b1  = b0 + HID;
        const float* b2  = b0 + 2 * HID;

        dim3 ggrid((NLOC + 127) / 128, 1, 3);
        gemm_tc_fused<<<ggrid, 256>>>(hsp, hloc, Wl, asl, ad2,
                                      PlocA, PspB, PlocC,
                                      als0, als1, als2, ald2);

        if (l == 0) {
            aggr_fused_kernel<<<AGGR_BLOCKS, 256>>>(rp_obs, cs_obs, rp_obsat, cs_obsat,
                                                    rp_near, cs_near,
                                                    als0, ald0, als1, ald1, als2, ald2,
                                                    PlocA, PspB, PlocC, hsp, hloc,
                                                    b0, b1, b2, hsp, hloc, 1,
                                                    wd + 1024, ald0, ald1);
        } else {
            aggr_fused_kernel<<<AGGR_BLOCKS, 256>>>(rp_obs, cs_obs, rp_obsat, cs_obsat,
                                                    rp_near, cs_near,
                                                    als0, ald0, als1, ald1, als2, ald2,
                                                    PlocA, PspB, PlocC, hsp, hloc,
                                                    b0, b1, b2, out, out + (size_t)NSP * HID, 0,
                                                    nullptr, nullptr, nullptr);
        }
    }
}